// round 6
// baseline (speedup 1.0000x reference)
#include <cuda_runtime.h>
#include <cuda_bf16.h>
#include <cstdint>

// NeuralNetwork_28819230556388 — B=262144, D=64, 13 chained 64x64 GEMMs.
// R6: main product bf16 mma.sync.m16n8k16 (A.hi x W.hi), corrections via
// fp8 e4m3 mma.sync.m16n8k32:
//   corr = e4m3(512*(A - bf16 A)) x e4m3(W)  +  e4m3(A) x e4m3(512*(W - bf16 W))
// accumulated together (shared 512 scale), folded with *1/512.
// 64 MMA-instr/matmul vs 96 -> tensor work x0.67. Expected rel_err ~1-3e-4.
// Correction GEMM uses a permuted k so C-frag pairs map straight into fp8
// A-frag bytes (no shuffles); W staged with the inverse permutation.
// Activations register-resident (2 slots), weights SMEM-resident, persistent CTAs.

#define TPB    256
#define GRID   148
#define NTILES 2048
#define INV512 0.001953125f

// SMEM layout (bytes)
#define OFF_BN 0                       // 7*64 f32
#define OFF_BS 1792                    // 6*64 f32
#define OFF_WH 4096                    // 13 * 8192: bf16 W.hi, ldmatrix layout
#define OFF_W8 (4096 + 13*8192)        // 13 * 8192: fp8 (hi kind +0, lo9 kind +4096)
#define SMEM_TOTAL (OFF_W8 + 13*8192)  // 217088

#define SMEM_SWIZZLE_128B(bo) ((bo) ^ (((bo) >> 3) & 0x70))

__device__ __forceinline__ uint32_t smem_to_u32(const void* p) {
    uint32_t a;
    asm("{ .reg .u64 t; cvta.to.shared.u64 t, %1; cvt.u32.u64 %0, t; }"
        : "=r"(a) : "l"(p));
    return a;
}

#define LDSM_X4(r, addr) \
    asm volatile("ldmatrix.sync.aligned.m8n8.x4.shared.b16 {%0,%1,%2,%3}, [%4];" \
        : "=r"((r)[0]), "=r"((r)[1]), "=r"((r)[2]), "=r"((r)[3]) \
        : "r"(addr))

__device__ __forceinline__ void mma_bf16(float d[4], const uint32_t a[4],
                                         uint32_t b0, uint32_t b1) {
    asm volatile(
        "mma.sync.aligned.m16n8k16.row.col.f32.bf16.bf16.f32 "
        "{%0,%1,%2,%3}, {%4,%5,%6,%7}, {%8,%9}, {%0,%1,%2,%3};"
        : "+f"(d[0]), "+f"(d[1]), "+f"(d[2]), "+f"(d[3])
        : "r"(a[0]), "r"(a[1]), "r"(a[2]), "r"(a[3]), "r"(b0), "r"(b1));
}

__device__ __forceinline__ void mma_e4m3(float d[4], const uint32_t a[4],
                                         uint32_t b0, uint32_t b1) {
    asm volatile(
        "mma.sync.aligned.m16n8k32.row.col.f32.e4m3.e4m3.f32 "
        "{%0,%1,%2,%3}, {%4,%5,%6,%7}, {%8,%9}, {%0,%1,%2,%3};"
        : "+f"(d[0]), "+f"(d[1]), "+f"(d[2]), "+f"(d[3])
        : "r"(a[0]), "r"(a[1]), "r"(a[2]), "r"(a[3]), "r"(b0), "r"(b1));
}

__device__ __forceinline__ uint2 lds64(uint32_t addr) {
    uint2 r;
    asm volatile("ld.shared.v2.u32 {%0,%1}, [%2];" : "=r"(r.x), "=r"(r.y) : "r"(addr));
    return r;
}

__device__ __forceinline__ uint32_t pk_bf16x2(float a, float b) {
    __nv_bfloat162 t = __floats2bfloat162_rn(a, b);
    return *reinterpret_cast<uint32_t*>(&t);
}
__device__ __forceinline__ float2 bf16x2_f2(uint32_t w) {
    __nv_bfloat162 t = *reinterpret_cast<__nv_bfloat162*>(&w);
    return make_float2(__bfloat162float(t.x), __bfloat162float(t.y));
}
// cvt packs FIRST source into the HIGH byte: result = {hi=a, lo=b}
__device__ __forceinline__ uint32_t cvt_e4m3x2(float hi, float lo) {
    uint16_t r;
    asm("cvt.rn.satfinite.e4m3x2.f32 %0, %1, %2;" : "=h"(r) : "f"(hi), "f"(lo));
    return (uint32_t)r;
}

// Activation fragment (16 rows x 64 cols per warp):
//  h   : bf16 A-frags [ktile16][4]
//  f8h : e4m3(value)        k32-frags [ktile32][4]  (permuted k)
//  f8l : e4m3(512*residual) k32-frags [ktile32][4]
struct Frag {
    uint32_t h[4][4];
    uint32_t f8h[2][4];
    uint32_t f8l[2][4];
};

// One layer. Ap = h_{t-1}; Aio = h_{t-2} on entry (skip operand), overwritten
// with h_t by pass 2's epilogue.  wh/w8 = next-weight bf16/fp8 bases;
// sh/s8 = skip-weight bases.
template <bool HAS_SKIP, bool LAST>
__device__ __forceinline__ void layer_step(
    const Frag& Ap, Frag& Aio,
    uint32_t wh, uint32_t w8, uint32_t sh, uint32_t s8,
    const float* __restrict__ bnp, const float* __restrict__ bsp,
    uint32_t soff0, uint32_t soff1, uint32_t lq, int qt,
    float* __restrict__ out0, float* __restrict__ out1)
{
    // ---- pass 1: skip GEMM (main bf16 + fp8 corr), staged in dsm ----
    float dsm[4][2][4];
    if (HAS_SKIP) {
#pragma unroll
        for (int np = 0; np < 4; ++np) {
            uint32_t B[2][8];
#pragma unroll
            for (int i2 = 0; i2 < 2; ++i2) {
                uint32_t a = sh + (uint32_t)(2 * np + i2) * 1024;
                LDSM_X4(&B[i2][0], a + soff0);
                LDSM_X4(&B[i2][4], a + soff1);
            }
#pragma unroll
            for (int i2 = 0; i2 < 2; ++i2)
#pragma unroll
                for (int r = 0; r < 4; ++r) dsm[np][i2][r] = 0.0f;
#pragma unroll
            for (int kt = 0; kt < 4; ++kt)
#pragma unroll
                for (int i2 = 0; i2 < 2; ++i2)
                    mma_bf16(dsm[np][i2], Aio.h[kt], B[i2][2 * kt], B[i2][2 * kt + 1]);

            float dc[2][4];
#pragma unroll
            for (int i2 = 0; i2 < 2; ++i2) {
#pragma unroll
                for (int r = 0; r < 4; ++r) dc[i2][r] = 0.0f;
                const uint32_t nb = s8 + (uint32_t)(2 * np + i2) * 512 + lq;
#pragma unroll
                for (int k8 = 0; k8 < 2; ++k8) {
                    uint2 whi = lds64(nb + (uint32_t)k8 * 256);
                    uint2 wlo = lds64(nb + (uint32_t)k8 * 256 + 4096);
                    mma_e4m3(dc[i2], Aio.f8l[k8], whi.x, whi.y);
                    mma_e4m3(dc[i2], Aio.f8h[k8], wlo.x, wlo.y);
                }
            }
#pragma unroll
            for (int i2 = 0; i2 < 2; ++i2)
#pragma unroll
                for (int r = 0; r < 4; ++r)
                    dsm[np][i2][r] += dc[i2][r] * INV512;
        }
    }

    // ---- pass 2: next GEMM per np + epilogue (writes Aio in place) ----
#pragma unroll
    for (int np = 0; np < 4; ++np) {
        uint32_t B[2][8];
#pragma unroll
        for (int i2 = 0; i2 < 2; ++i2) {
            uint32_t a = wh + (uint32_t)(2 * np + i2) * 1024;
            LDSM_X4(&B[i2][0], a + soff0);
            LDSM_X4(&B[i2][4], a + soff1);
        }
        float dn[2][4], dc[2][4];
#pragma unroll
        for (int i2 = 0; i2 < 2; ++i2)
#pragma unroll
            for (int r = 0; r < 4; ++r) { dn[i2][r] = 0.0f; dc[i2][r] = 0.0f; }
#pragma unroll
        for (int kt = 0; kt < 4; ++kt)
#pragma unroll
            for (int i2 = 0; i2 < 2; ++i2)
                mma_bf16(dn[i2], Ap.h[kt], B[i2][2 * kt], B[i2][2 * kt + 1]);
#pragma unroll
        for (int i2 = 0; i2 < 2; ++i2) {
            const uint32_t nb = w8 + (uint32_t)(2 * np + i2) * 512 + lq;
#pragma unroll
            for (int k8 = 0; k8 < 2; ++k8) {
                uint2 whi = lds64(nb + (uint32_t)k8 * 256);
                uint2 wlo = lds64(nb + (uint32_t)k8 * 256 + 4096);
                mma_e4m3(dc[i2], Ap.f8l[k8], whi.x, whi.y);
                mma_e4m3(dc[i2], Ap.f8h[k8], wlo.x, wlo.y);
            }
        }

        // epilogue: v = relu(main + corr/512 + b) (+ relu(skip...)), pack
        uint32_t lh0 = 0, lh1 = 0, ll0 = 0, ll1 = 0;   // i2==0 halves
#pragma unroll
        for (int i2 = 0; i2 < 2; ++i2) {
            const int nt = 2 * np + i2;
            float b0 = bnp[8 * nt + 2 * qt];
            float b1 = bnp[8 * nt + 2 * qt + 1];
            float v0 = fmaxf(dn[i2][0] + dc[i2][0] * INV512 + b0, 0.0f);
            float v1 = fmaxf(dn[i2][1] + dc[i2][1] * INV512 + b1, 0.0f);
            float v2 = fmaxf(dn[i2][2] + dc[i2][2] * INV512 + b0, 0.0f);
            float v3 = fmaxf(dn[i2][3] + dc[i2][3] * INV512 + b1, 0.0f);
            if (HAS_SKIP) {
                float s0 = bsp[8 * nt + 2 * qt];
                float s1 = bsp[8 * nt + 2 * qt + 1];
                v0 += fmaxf(dsm[np][i2][0] + s0, 0.0f);
                v1 += fmaxf(dsm[np][i2][1] + s1, 0.0f);
                v2 += fmaxf(dsm[np][i2][2] + s0, 0.0f);
                v3 += fmaxf(dsm[np][i2][3] + s1, 0.0f);
            }
            if (LAST) {
                *reinterpret_cast<float2*>(out0 + 8 * nt + 2 * qt) = make_float2(v0, v1);
                *reinterpret_cast<float2*>(out1 + 8 * nt + 2 * qt) = make_float2(v2, v3);
            } else {
                uint32_t h01 = pk_bf16x2(v0, v1);
                uint32_t h23 = pk_bf16x2(v2, v3);
                Aio.h[np][2 * i2]     = h01;
                Aio.h[np][2 * i2 + 1] = h23;
                float2 f01 = bf16x2_f2(h01);
                float2 f23 = bf16x2_f2(h23);
                uint32_t ch0 = cvt_e4m3x2(v1, v0);                       // row0
                uint32_t ch1 = cvt_e4m3x2(v3, v2);                       // row1
                uint32_t cl0 = cvt_e4m3x2((v1 - f01.y) * 512.f, (v0 - f01.x) * 512.f);
                uint32_t cl1 = cvt_e4m3x2((v3 - f23.y) * 512.f, (v2 - f23.x) * 512.f);
                if (i2 == 0) { lh0 = ch0; lh1 = ch1; ll0 = cl0; ll1 = cl1; }
                else {
                    const int K8 = np >> 1, RB = (np & 1) * 2;
                    Aio.f8h[K8][RB]     = lh0 | (ch0 << 16);
                    Aio.f8h[K8][RB + 1] = lh1 | (ch1 << 16);
                    Aio.f8l[K8][RB]     = ll0 | (cl0 << 16);
                    Aio.f8l[K8][RB + 1] = ll1 | (cl1 << 16);
                }
            }
        }
    }
}

__global__ void __launch_bounds__(TPB, 1)
nn_mma_kernel(const float* __restrict__ x,
              const float* __restrict__ Wn_g,
              const float* __restrict__ bn_g,
              const float* __restrict__ Ws_g,
              const float* __restrict__ bs_g,
              float* __restrict__ out)
{
    extern __shared__ unsigned char sm[];
    const uint32_t smb = smem_to_u32(sm);
    const int tid  = threadIdx.x;
    const int wid  = tid >> 5;
    const int lane = tid & 31;
    const int qt   = lane & 3;
    const int grp  = lane >> 2;

    // ---- stage weights: bf16 hi (ldmatrix layout) + fp8 hi/lo9 (frag layout,
    //      permuted k: p = 32*kt8 + 16*half + 4*qt + 2*pos + j) ----
    for (int idx = tid; idx < 13 * 4096; idx += TPB) {
        int mat = idx >> 12, e = idx & 4095;
        float v = (mat < 7) ? Wn_g[mat * 4096 + e] : Ws_g[(mat - 7) * 4096 + e];
        __nv_bfloat16 hb = __float2bfloat16(v);
        float hf = __bfloat162float(hb);
        int n = e >> 6, c = e & 63;
        uint32_t sw = SMEM_SWIZZLE_128B((uint32_t)(n * 128 + c * 2));
        *reinterpret_cast<__nv_bfloat16*>(sm + OFF_WH + mat * 8192 + sw) = hb;

        uint8_t f8h = (uint8_t)cvt_e4m3x2(0.0f, v);
        uint8_t f8l = (uint8_t)cvt_e4m3x2(0.0f, (v - hf) * 512.0f);
        int ntp = c >> 3, q = (c >> 1) & 3, j = c & 1;
        int kt8 = ntp >> 2, half = (ntp >> 1) & 1, pos = ntp & 1;
        int ntile = n >> 3, nin = n & 7;
        uint32_t a8 = OFF_W8 + (uint32_t)mat * 8192 + (uint32_t)ntile * 512 +
                      (uint32_t)kt8 * 256 + (uint32_t)nin * 32 + (uint32_t)q * 8 +
                      (uint32_t)half * 4 + (uint32_t)pos * 2 + (uint32_t)j;
        sm[a8]        = (unsigned char)f8h;
        sm[a8 + 4096] = (unsigned char)f8l;
    }
    for (int i = tid; i < 448; i += TPB)
        reinterpret_cast<float*>(sm + OFF_BN)[i] = bn_g[i];
    for (int i = tid; i < 384; i += TPB)
        reinterpret_cast<float*>(sm + OFF_BS)[i] = bs_g[i];
    __syncthreads();

    // ldmatrix swizzled per-thread offsets (k halves 0-31 / 32-63)
    const int r8 = lane & 7, b4 = lane >> 3;
    const uint32_t soff0 = (uint32_t)(r8 * 128 + ((b4 * 16)      ^ (r8 * 16)));
    const uint32_t soff1 = (uint32_t)(r8 * 128 + ((b4 * 16 + 64) ^ (r8 * 16)));
    // fp8 B-frag per-thread offset (LDS.64, conflict-free)
    const uint32_t lq = (uint32_t)grp * 32 + (uint32_t)qt * 8;

    const float* bn = reinterpret_cast<const float*>(sm + OFF_BN);
    const float* bs = reinterpret_cast<const float*>(sm + OFF_BS);
    const uint32_t wh0 = smb + OFF_WH;
    const uint32_t w80 = smb + OFF_W8;

    const int row0 = wid * 16 + grp;
    const int row1 = row0 + 8;

    for (int tile = blockIdx.x; tile < NTILES; tile += GRID) {
        const size_t gr0 = (size_t)tile * 128 + row0;
        const size_t gr1 = (size_t)tile * 128 + row1;

        Frag A0, A1;

        // ---- load x -> A0 (bf16 hi + fp8 frags) ----
        {
            const float* xr0 = x + gr0 * 64;
            const float* xr1 = x + gr1 * 64;
#pragma unroll
            for (int kt = 0; kt < 4; ++kt) {
                const int c = 16 * kt + 2 * qt;
                float2 p0 = *reinterpret_cast<const float2*>(xr0 + c);       // nt=2kt row0
                float2 p1 = *reinterpret_cast<const float2*>(xr1 + c);       // nt=2kt row1
                float2 p2 = *reinterpret_cast<const float2*>(xr0 + c + 8);   // nt=2kt+1 row0
                float2 p3 = *reinterpret_cast<const float2*>(xr1 + c + 8);   // nt=2kt+1 row1
                uint32_t h0 = pk_bf16x2(p0.x, p0.y);
                uint32_t h1 = pk_bf16x2(p1.x, p1.y);
                uint32_t h2 = pk_bf16x2(p2.x, p2.y);
                uint32_t h3 = pk_bf16x2(p3.x, p3.y);
                A0.h[kt][0] = h0; A0.h[kt][1] = h1; A0.h[kt][2] = h2; A0.h[kt][3] = h3;
                float2 f0 = bf16x2_f2(h0), f1 = bf16x2_f2(h1);
                float2 f2 = bf16x2_f2(h2), f3 = bf16x2_f2(h3);
                const int K8 = kt >> 1, RB = (kt & 1) * 2;
                A0.f8h[K8][RB]     = cvt_e4m3x2(p0.y, p0.x) | (cvt_e4m3x2(p2.y, p2.x) << 16);
                A0.f8h[K8][RB + 1] = cvt_e4m3x2(p1.y, p1.x) | (cvt_e4m3x2(p3.y, p3.x) << 16);
                A0.f8l[K8][RB]     = cvt_e4m3x2((p0.y - f0.y) * 512.f, (p0.x - f0.x) * 512.f) |
                                     (cvt_e4m3x2((p2.y - f2.y) * 512.f, (p2.x - f2.x) * 512.f) << 16);
                A0.f8l[K8][RB + 1] = cvt_e4m3x2((p1.y - f1.y) * 512.f, (p1.x - f1.x) * 512.f) |
                                     (cvt_e4m3x2((p3.y - f3.y) * 512.f, (p3.x - f3.x) * 512.f) << 16);
            }
        }

        float* o0 = out + gr0 * 64;
        float* o1 = out + gr1 * 64;

#define WH(m) (wh0 + (m) * 8192u)
#define W8(m) (w80 + (m) * 8192u)
        layer_step<false, false>(A0, A1, WH(0), W8(0), 0, 0,
                                 bn + 0 * 64, bs, soff0, soff1, lq, qt, o0, o1);
        layer_step<true,  false>(A1, A0, WH(1), W8(1), WH(7), W8(7),
                                 bn + 1 * 64, bs + 0 * 64, soff0, soff1, lq, qt, o0, o1);
        layer_step<true,  false>(A0, A1, WH(2), W8(2), WH(8), W8(8),
                                 bn + 2 * 64, bs + 1 * 64, soff0, soff1, lq, qt, o0, o1);
        layer_step<true,  false>(A1, A0, WH(3), W8(3), WH(9), W8(9),
                                 bn + 3 * 64, bs + 2 * 64, soff0, soff1, lq, qt, o0, o1);
        layer_step<true,  false>(A0, A1, WH(4), W8(4), WH(10), W8(10),
                                 bn + 4 * 64, bs + 3 * 64, soff0, soff1, lq, qt, o0, o1);
        layer_step<true,  false>(A1, A0, WH(5), W8(5), WH(11), W8(11),
                                 bn + 5 * 64, bs + 4 * 64, soff0, soff1, lq, qt, o0, o1);
        layer_step<true,  true >(A0, A1, WH(6), W8(6), WH(12), W8(12),
                                 bn + 6 * 64, bs + 5 * 64, soff0, soff1, lq, qt, o0, o1);
#undef WH
#undef W8
    }
}

extern "C" void kernel_launch(void* const* d_in, const int* in_sizes, int n_in,
                              void* d_out, int out_size)
{
    const float* x  = (const float*)d_in[0];
    const float* Wn = (const float*)d_in[1];
    const float* bn = (const float*)d_in[2];
    const float* Ws = (const float*)d_in[3];
    const float* bs = (const float*)d_in[4];
    float* out = (float*)d_out;

    cudaFuncSetAttribute(nn_mma_kernel,
                         cudaFuncAttributeMaxDynamicSharedMemorySize, SMEM_TOTAL);
    nn_mma_kernel<<<GRID, TPB, SMEM_TOTAL>>>(x, Wn, bn, Ws, bs, out);
}

// round 7
// speedup vs baseline: 1.9693x; 1.9693x over previous
#include <cuda_runtime.h>
#include <cuda_bf16.h>
#include <cstdint>

// NeuralNetwork_28819230556388 — B=262144, D=64, 13 chained 64x64 GEMMs.
// R7: bf16 3-product split (R5 arithmetic, rel_err ~6e-6) at HIGHER OCCUPANCY:
// TPB=384 (3 warps/SMSP, reg cap 170) to hide the epilogue/LDSM phases under
// other warps' HMMA streams. Layer restructured for the register budget:
// next+skip GEMMs fused per n-tile (B transient), epilogue deferred to layer
// end (dn+ds = 64 accum regs), two-slot in-place activation rotation.
// Warps fully independent: global warp-strided loop over 16-row groups.

#define TPB     384
#define GRID    148
#define NGROUPS 16384                 // 262144 / 16
#define WSTEP   (GRID * (TPB / 32))   // 1776 warps in flight

// SMEM layout (bytes)
#define OFF_BN 0                     // 7*64 f32 = 1792
#define OFF_BS 1792                  // 6*64 f32 = 1536
#define OFF_W  4096                  // 13 mats * 16384 (hi at +0, lo at +8192)
#define SMEM_TOTAL (4096 + 26*8192)  // 217088

#define SMEM_SWIZZLE_128B(bo) ((bo) ^ (((bo) >> 3) & 0x70))

__device__ __forceinline__ uint32_t smem_to_u32(const void* p) {
    uint32_t a;
    asm("{ .reg .u64 t; cvta.to.shared.u64 t, %1; cvt.u32.u64 %0, t; }"
        : "=r"(a) : "l"(p));
    return a;
}

#define LDSM_X4(r, addr) \
    asm volatile("ldmatrix.sync.aligned.m8n8.x4.shared.b16 {%0,%1,%2,%3}, [%4];" \
        : "=r"((r)[0]), "=r"((r)[1]), "=r"((r)[2]), "=r"((r)[3]) \
        : "r"(addr))

__device__ __forceinline__ void mma_bf16(float d[4], const uint32_t a[4],
                                         uint32_t b0, uint32_t b1) {
    asm volatile(
        "mma.sync.aligned.m16n8k16.row.col.f32.bf16.bf16.f32 "
        "{%0,%1,%2,%3}, {%4,%5,%6,%7}, {%8,%9}, {%0,%1,%2,%3};"
        : "+f"(d[0]), "+f"(d[1]), "+f"(d[2]), "+f"(d[3])
        : "r"(a[0]), "r"(a[1]), "r"(a[2]), "r"(a[3]), "r"(b0), "r"(b1));
}

// split (a,b) into bf16 hi pair + bf16 residual pair (packed b32, a low)
__device__ __forceinline__ void pack_split(float a, float b,
                                           uint32_t& hi, uint32_t& lo) {
    __nv_bfloat162 h = __floats2bfloat162_rn(a, b);
    float ra = a - __bfloat162float(h.x);
    float rb = b - __bfloat162float(h.y);
    __nv_bfloat162 l = __floats2bfloat162_rn(ra, rb);
    hi = *reinterpret_cast<uint32_t*>(&h);
    lo = *reinterpret_cast<uint32_t*>(&l);
}

// 16 rows x 64 cols activation fragment, bf16 hi/lo A-frags [ktile][reg]
struct Frag {
    uint32_t h[4][4];
    uint32_t l[4][4];
};

// One layer. Ap = h_{t-1}. Aio = h_{t-2} on entry (skip operand); the deferred
// epilogue overwrites it with h_t AFTER all skip MMAs have consumed it.
template <bool HAS_SKIP, bool LAST>
__device__ __forceinline__ void layer_step(
    const Frag& Ap, Frag& Aio,
    uint32_t wn, uint32_t ws,
    const float* __restrict__ bnp, const float* __restrict__ bsp,
    uint32_t soff0, uint32_t soff1, int qt,
    float* __restrict__ out0, float* __restrict__ out1)
{
    float dn[4][2][4];
    float ds[4][2][4];

    // ---- GEMM phase: per n-tile pair, next then skip, 3 products each ----
#pragma unroll
    for (int np = 0; np < 4; ++np) {
        uint32_t B[2][8];
        // next: W.hi
#pragma unroll
        for (int i2 = 0; i2 < 2; ++i2) {
            uint32_t a = wn + (uint32_t)(2 * np + i2) * 1024;
            LDSM_X4(&B[i2][0], a + soff0);
            LDSM_X4(&B[i2][4], a + soff1);
        }
#pragma unroll
        for (int i2 = 0; i2 < 2; ++i2)
#pragma unroll
            for (int r = 0; r < 4; ++r) dn[np][i2][r] = 0.0f;
#pragma unroll
        for (int kt = 0; kt < 4; ++kt)
#pragma unroll
            for (int i2 = 0; i2 < 2; ++i2)
                mma_bf16(dn[np][i2], Ap.h[kt], B[i2][2 * kt], B[i2][2 * kt + 1]);
#pragma unroll
        for (int kt = 0; kt < 4; ++kt)
#pragma unroll
            for (int i2 = 0; i2 < 2; ++i2)
                mma_bf16(dn[np][i2], Ap.l[kt], B[i2][2 * kt], B[i2][2 * kt + 1]);
        // next: W.lo
#pragma unroll
        for (int i2 = 0; i2 < 2; ++i2) {
            uint32_t a = wn + 8192u + (uint32_t)(2 * np + i2) * 1024;
            LDSM_X4(&B[i2][0], a + soff0);
            LDSM_X4(&B[i2][4], a + soff1);
        }
#pragma unroll
        for (int kt = 0; kt < 4; ++kt)
#pragma unroll
            for (int i2 = 0; i2 < 2; ++i2)
                mma_bf16(dn[np][i2], Ap.h[kt], B[i2][2 * kt], B[i2][2 * kt + 1]);

        if (HAS_SKIP) {
            // skip: W.hi
#pragma unroll
            for (int i2 = 0; i2 < 2; ++i2) {
                uint32_t s = ws + (uint32_t)(2 * np + i2) * 1024;
                LDSM_X4(&B[i2][0], s + soff0);
                LDSM_X4(&B[i2][4], s + soff1);
            }
#pragma unroll
            for (int i2 = 0; i2 < 2; ++i2)
#pragma unroll
                for (int r = 0; r < 4; ++r) ds[np][i2][r] = 0.0f;
#pragma unroll
            for (int kt = 0; kt < 4; ++kt)
#pragma unroll
                for (int i2 = 0; i2 < 2; ++i2)
                    mma_bf16(ds[np][i2], Aio.h[kt], B[i2][2 * kt], B[i2][2 * kt + 1]);
#pragma unroll
            for (int kt = 0; kt < 4; ++kt)
#pragma unroll
                for (int i2 = 0; i2 < 2; ++i2)
                    mma_bf16(ds[np][i2], Aio.l[kt], B[i2][2 * kt], B[i2][2 * kt + 1]);
            // skip: W.lo
#pragma unroll
            for (int i2 = 0; i2 < 2; ++i2) {
                uint32_t s = ws + 8192u + (uint32_t)(2 * np + i2) * 1024;
                LDSM_X4(&B[i2][0], s + soff0);
                LDSM_X4(&B[i2][4], s + soff1);
            }
#pragma unroll
            for (int kt = 0; kt < 4; ++kt)
#pragma unroll
                for (int i2 = 0; i2 < 2; ++i2)
                    mma_bf16(ds[np][i2], Aio.h[kt], B[i2][2 * kt], B[i2][2 * kt + 1]);
        }
    }

    // ---- deferred epilogue: bias + relu (+skip), pack into Aio in place ----
#pragma unroll
    for (int np = 0; np < 4; ++np)
#pragma unroll
        for (int i2 = 0; i2 < 2; ++i2) {
            const int nt = 2 * np + i2;
            float b0 = bnp[8 * nt + 2 * qt];
            float b1 = bnp[8 * nt + 2 * qt + 1];
            float v0 = fmaxf(dn[np][i2][0] + b0, 0.0f);
            float v1 = fmaxf(dn[np][i2][1] + b1, 0.0f);
            float v2 = fmaxf(dn[np][i2][2] + b0, 0.0f);
            float v3 = fmaxf(dn[np][i2][3] + b1, 0.0f);
            if (HAS_SKIP) {
                float s0 = bsp[8 * nt + 2 * qt];
                float s1 = bsp[8 * nt + 2 * qt + 1];
                v0 += fmaxf(ds[np][i2][0] + s0, 0.0f);
                v1 += fmaxf(ds[np][i2][1] + s1, 0.0f);
                v2 += fmaxf(ds[np][i2][2] + s0, 0.0f);
                v3 += fmaxf(ds[np][i2][3] + s1, 0.0f);
            }
            if (LAST) {
                *reinterpret_cast<float2*>(out0 + 8 * nt + 2 * qt) = make_float2(v0, v1);
                *reinterpret_cast<float2*>(out1 + 8 * nt + 2 * qt) = make_float2(v2, v3);
            } else {
                pack_split(v0, v1, Aio.h[np][2 * i2],     Aio.l[np][2 * i2]);
                pack_split(v2, v3, Aio.h[np][2 * i2 + 1], Aio.l[np][2 * i2 + 1]);
            }
        }
}

__global__ void __launch_bounds__(TPB, 1)
nn_mma_kernel(const float* __restrict__ x,
              const float* __restrict__ Wn_g,
              const float* __restrict__ bn_g,
              const float* __restrict__ Ws_g,
              const float* __restrict__ bs_g,
              float* __restrict__ out)
{
    extern __shared__ unsigned char sm[];
    const uint32_t smb = smem_to_u32(sm);
    const int tid  = threadIdx.x;
    const int wid  = tid >> 5;
    const int lane = tid & 31;
    const int qt   = lane & 3;
    const int grp  = lane >> 2;

    // ---- stage 13 weight matrices as bf16 hi/lo, [n][k] row-major, SW128 ----
    for (int idx = tid; idx < 13 * 4096; idx += TPB) {
        int mat = idx >> 12, e = idx & 4095;
        float v = (mat < 7) ? Wn_g[mat * 4096 + e] : Ws_g[(mat - 7) * 4096 + e];
        __nv_bfloat16 hb = __float2bfloat16(v);
        __nv_bfloat16 lb = __float2bfloat16(v - __bfloat162float(hb));
        int n = e >> 6, k = e & 63;
        uint32_t sw = SMEM_SWIZZLE_128B((uint32_t)(n * 128 + k * 2));
        uint32_t base = OFF_W + (uint32_t)mat * 16384;
        *reinterpret_cast<__nv_bfloat16*>(sm + base + sw)        = hb;
        *reinterpret_cast<__nv_bfloat16*>(sm + base + 8192 + sw) = lb;
    }
    for (int i = tid; i < 448; i += TPB)
        reinterpret_cast<float*>(sm + OFF_BN)[i] = bn_g[i];
    for (int i = tid; i < 384; i += TPB)
        reinterpret_cast<float*>(sm + OFF_BS)[i] = bs_g[i];
    __syncthreads();

    // per-thread ldmatrix.x4 swizzled offsets (k halves 0-31 / 32-63)
    const int r8 = lane & 7, b4 = lane >> 3;
    const uint32_t soff0 = (uint32_t)(r8 * 128 + ((b4 * 16)      ^ (r8 * 16)));
    const uint32_t soff1 = (uint32_t)(r8 * 128 + ((b4 * 16 + 64) ^ (r8 * 16)));

    const float* bn = reinterpret_cast<const float*>(sm + OFF_BN);
    const float* bs = reinterpret_cast<const float*>(sm + OFF_BS);
    const uint32_t w0 = smb + OFF_W;

    // warps are independent: global warp-strided loop over 16-row groups
    const int gw = blockIdx.x * (TPB / 32) + wid;

    for (int g = gw; g < NGROUPS; g += WSTEP) {
        const size_t gr0 = (size_t)g * 16 + grp;
        const size_t gr1 = gr0 + 8;

        Frag A0, A1;   // two slots; h_t overwrites the slot holding h_{t-2}

        // ---- load x -> A0 (hi/lo) directly from gmem ----
        {
            const float* xr0 = x + gr0 * 64;
            const float* xr1 = x + gr1 * 64;
#pragma unroll
            for (int kt = 0; kt < 4; ++kt) {
                const int c = 16 * kt + 2 * qt;
                float2 p0 = *reinterpret_cast<const float2*>(xr0 + c);
                float2 p1 = *reinterpret_cast<const float2*>(xr1 + c);
                float2 p2 = *reinterpret_cast<const float2*>(xr0 + c + 8);
                float2 p3 = *reinterpret_cast<const float2*>(xr1 + c + 8);
                pack_split(p0.x, p0.y, A0.h[kt][0], A0.l[kt][0]);
                pack_split(p1.x, p1.y, A0.h[kt][1], A0.l[kt][1]);
                pack_split(p2.x, p2.y, A0.h[kt][2], A0.l[kt][2]);
                pack_split(p3.x, p3.y, A0.h[kt][3], A0.l[kt][3]);
            }
        }

        float* o0 = out + gr0 * 64;
        float* o1 = out + gr1 * 64;

        // layer t: Ap = h_{t-1}, Aio = h_{t-2} -> h_t
        layer_step<false, false>(A0, A1, w0 + 0 * 16384, 0,
                                 bn + 0 * 64, bs, soff0, soff1, qt, o0, o1);           // h1 -> A1
        layer_step<true,  false>(A1, A0, w0 + 1 * 16384, w0 + 7 * 16384,
                                 bn + 1 * 64, bs + 0 * 64, soff0, soff1, qt, o0, o1);  // h2 -> A0
        layer_step<true,  false>(A0, A1, w0 + 2 * 16384, w0 + 8 * 16384,
                                 bn + 2 * 64, bs + 1 * 64, soff0, soff1, qt, o0, o1);  // h3 -> A1
        layer_step<true,  false>(A1, A0, w0 + 3 * 16384, w0 + 9 * 16384,
                                 bn + 3 * 64, bs + 2 * 64, soff0, soff1, qt, o0, o1);  // h4 -> A0
        layer_step<true,  false>(A0, A1, w0 + 4 * 16384, w0 + 10 * 16384,
                                 bn + 4 * 64, bs + 3 * 64, soff0, soff1, qt, o0, o1);  // h5 -> A1
        layer_step<true,  false>(A1, A0, w0 + 5 * 16384, w0 + 11 * 16384,
                                 bn + 5 * 64, bs + 4 * 64, soff0, soff1, qt, o0, o1);  // h6 -> A0
        layer_step<true,  true >(A0, A1, w0 + 6 * 16384, w0 + 12 * 16384,
                                 bn + 6 * 64, bs + 5 * 64, soff0, soff1, qt, o0, o1);  // h7 -> out
    }
}

extern "C" void kernel_launch(void* const* d_in, const int* in_sizes, int n_in,
                              void* d_out, int out_size)
{
    const float* x  = (const float*)d_in[0];
    const float* Wn = (const float*)d_in[1];
    const float* bn = (const float*)d_in[2];
    const float* Ws = (const float*)d_in[3];
    const float* bs = (const float*)d_in[4];
    float* out = (float*)d_out;

    cudaFuncSetAttribute(nn_mma_kernel,
                         cudaFuncAttributeMaxDynamicSharedMemorySize, SMEM_TOTAL);
    nn_mma_kernel<<<GRID, TPB, SMEM_TOTAL>>>(x, Wn, bn, Ws, bs, out);
}

// round 8
// speedup vs baseline: 1.9734x; 1.0021x over previous
#include <cuda_runtime.h>
#include <cuda_bf16.h>
#include <cstdint>

// NeuralNetwork_28819230556388 — B=262144, D=64, 13 chained 64x64 GEMMs.
// R7: bf16 3-product split (R5 arithmetic, rel_err ~6e-6) at HIGHER OCCUPANCY:
// TPB=384 (3 warps/SMSP, reg cap 170) to hide the epilogue/LDSM phases under
// other warps' HMMA streams. Layer restructured for the register budget:
// next+skip GEMMs fused per n-tile (B transient), epilogue deferred to layer
// end (dn+ds = 64 accum regs), two-slot in-place activation rotation.
// Warps fully independent: global warp-strided loop over 16-row groups.

#define TPB     384
#define GRID    148
#define NGROUPS 16384                 // 262144 / 16
#define WSTEP   (GRID * (TPB / 32))   // 1776 warps in flight

// SMEM layout (bytes)
#define OFF_BN 0                     // 7*64 f32 = 1792
#define OFF_BS 1792                  // 6*64 f32 = 1536
#define OFF_W  4096                  // 13 mats * 16384 (hi at +0, lo at +8192)
#define SMEM_TOTAL (4096 + 26*8192)  // 217088

#define SMEM_SWIZZLE_128B(bo) ((bo) ^ (((bo) >> 3) & 0x70))

__device__ __forceinline__ uint32_t smem_to_u32(const void* p) {
    uint32_t a;
    asm("{ .reg .u64 t; cvta.to.shared.u64 t, %1; cvt.u32.u64 %0, t; }"
        : "=r"(a) : "l"(p));
    return a;
}

#define LDSM_X4(r, addr) \
    asm volatile("ldmatrix.sync.aligned.m8n8.x4.shared.b16 {%0,%1,%2,%3}, [%4];" \
        : "=r"((r)[0]), "=r"((r)[1]), "=r"((r)[2]), "=r"((r)[3]) \
        : "r"(addr))

__device__ __forceinline__ void mma_bf16(float d[4], const uint32_t a[4],
                                         uint32_t b0, uint32_t b1) {
    asm volatile(
        "mma.sync.aligned.m16n8k16.row.col.f32.bf16.bf16.f32 "
        "{%0,%1,%2,%3}, {%4,%5,%6,%7}, {%8,%9}, {%0,%1,%2,%3};"
        : "+f"(d[0]), "+f"(d[1]), "+f"(d[2]), "+f"(d[3])
        : "r"(a[0]), "r"(a[1]), "r"(a[2]), "r"(a[3]), "r"(b0), "r"(b1));
}

// split (a,b) into bf16 hi pair + bf16 residual pair (packed b32, a low)
__device__ __forceinline__ void pack_split(float a, float b,
                                           uint32_t& hi, uint32_t& lo) {
    __nv_bfloat162 h = __floats2bfloat162_rn(a, b);
    float ra = a - __bfloat162float(h.x);
    float rb = b - __bfloat162float(h.y);
    __nv_bfloat162 l = __floats2bfloat162_rn(ra, rb);
    hi = *reinterpret_cast<uint32_t*>(&h);
    lo = *reinterpret_cast<uint32_t*>(&l);
}

// 16 rows x 64 cols activation fragment, bf16 hi/lo A-frags [ktile][reg]
struct Frag {
    uint32_t h[4][4];
    uint32_t l[4][4];
};

// One layer. Ap = h_{t-1}. Aio = h_{t-2} on entry (skip operand); the deferred
// epilogue overwrites it with h_t AFTER all skip MMAs have consumed it.
template <bool HAS_SKIP, bool LAST>
__device__ __forceinline__ void layer_step(
    const Frag& Ap, Frag& Aio,
    uint32_t wn, uint32_t ws,
    const float* __restrict__ bnp, const float* __restrict__ bsp,
    uint32_t soff0, uint32_t soff1, int qt,
    float* __restrict__ out0, float* __restrict__ out1)
{
    float dn[4][2][4];
    float ds[4][2][4];

    // ---- GEMM phase: per n-tile pair, next then skip, 3 products each ----
#pragma unroll
    for (int np = 0; np < 4; ++np) {
        uint32_t B[2][8];
        // next: W.hi
#pragma unroll
        for (int i2 = 0; i2 < 2; ++i2) {
            uint32_t a = wn + (uint32_t)(2 * np + i2) * 1024;
            LDSM_X4(&B[i2][0], a + soff0);
            LDSM_X4(&B[i2][4], a + soff1);
        }
#pragma unroll
        for (int i2 = 0; i2 < 2; ++i2)
#pragma unroll
            for (int r = 0; r < 4; ++r) dn[np][i2][r] = 0.0f;
#pragma unroll
        for (int kt = 0; kt < 4; ++kt)
#pragma unroll
            for (int i2 = 0; i2 < 2; ++i2)
                mma_bf16(dn[np][i2], Ap.h[kt], B[i2][2 * kt], B[i2][2 * kt + 1]);
#pragma unroll
        for (int kt = 0; kt < 4; ++kt)
#pragma unroll
            for (int i2 = 0; i2 < 2; ++i2)
                mma_bf16(dn[np][i2], Ap.l[kt], B[i2][2 * kt], B[i2][2 * kt + 1]);
        // next: W.lo
#pragma unroll
        for (int i2 = 0; i2 < 2; ++i2) {
            uint32_t a = wn + 8192u + (uint32_t)(2 * np + i2) * 1024;
            LDSM_X4(&B[i2][0], a + soff0);
            LDSM_X4(&B[i2][4], a + soff1);
        }
#pragma unroll
        for (int kt = 0; kt < 4; ++kt)
#pragma unroll
            for (int i2 = 0; i2 < 2; ++i2)
                mma_bf16(dn[np][i2], Ap.h[kt], B[i2][2 * kt], B[i2][2 * kt + 1]);

        if (HAS_SKIP) {
            // skip: W.hi
#pragma unroll
            for (int i2 = 0; i2 < 2; ++i2) {
                uint32_t s = ws + (uint32_t)(2 * np + i2) * 1024;
                LDSM_X4(&B[i2][0], s + soff0);
                LDSM_X4(&B[i2][4], s + soff1);
            }
#pragma unroll
            for (int i2 = 0; i2 < 2; ++i2)
#pragma unroll
                for (int r = 0; r < 4; ++r) ds[np][i2][r] = 0.0f;
#pragma unroll
            for (int kt = 0; kt < 4; ++kt)
#pragma unroll
                for (int i2 = 0; i2 < 2; ++i2)
                    mma_bf16(ds[np][i2], Aio.h[kt], B[i2][2 * kt], B[i2][2 * kt + 1]);
#pragma unroll
            for (int kt = 0; kt < 4; ++kt)
#pragma unroll
                for (int i2 = 0; i2 < 2; ++i2)
                    mma_bf16(ds[np][i2], Aio.l[kt], B[i2][2 * kt], B[i2][2 * kt + 1]);
            // skip: W.lo
#pragma unroll
            for (int i2 = 0; i2 < 2; ++i2) {
                uint32_t s = ws + 8192u + (uint32_t)(2 * np + i2) * 1024;
                LDSM_X4(&B[i2][0], s + soff0);
                LDSM_X4(&B[i2][4], s + soff1);
            }
#pragma unroll
            for (int kt = 0; kt < 4; ++kt)
#pragma unroll
                for (int i2 = 0; i2 < 2; ++i2)
                    mma_bf16(ds[np][i2], Aio.h[kt], B[i2][2 * kt], B[i2][2 * kt + 1]);
        }
    }

    // ---- deferred epilogue: bias + relu (+skip), pack into Aio in place ----
#pragma unroll
    for (int np = 0; np < 4; ++np)
#pragma unroll
        for (int i2 = 0; i2 < 2; ++i2) {
            const int nt = 2 * np + i2;
            float b0 = bnp[8 * nt + 2 * qt];
            float b1 = bnp[8 * nt + 2 * qt + 1];
            float v0 = fmaxf(dn[np][i2][0] + b0, 0.0f);
            float v1 = fmaxf(dn[np][i2][1] + b1, 0.0f);
            float v2 = fmaxf(dn[np][i2][2] + b0, 0.0f);
            float v3 = fmaxf(dn[np][i2][3] + b1, 0.0f);
            if (HAS_SKIP) {
                float s0 = bsp[8 * nt + 2 * qt];
                float s1 = bsp[8 * nt + 2 * qt + 1];
                v0 += fmaxf(ds[np][i2][0] + s0, 0.0f);
                v1 += fmaxf(ds[np][i2][1] + s1, 0.0f);
                v2 += fmaxf(ds[np][i2][2] + s0, 0.0f);
                v3 += fmaxf(ds[np][i2][3] + s1, 0.0f);
            }
            if (LAST) {
                *reinterpret_cast<float2*>(out0 + 8 * nt + 2 * qt) = make_float2(v0, v1);
                *reinterpret_cast<float2*>(out1 + 8 * nt + 2 * qt) = make_float2(v2, v3);
            } else {
                pack_split(v0, v1, Aio.h[np][2 * i2],     Aio.l[np][2 * i2]);
                pack_split(v2, v3, Aio.h[np][2 * i2 + 1], Aio.l[np][2 * i2 + 1]);
            }
        }
}

__global__ void __launch_bounds__(TPB, 1)
nn_mma_kernel(const float* __restrict__ x,
              const float* __restrict__ Wn_g,
              const float* __restrict__ bn_g,
              const float* __restrict__ Ws_g,
              const float* __restrict__ bs_g,
              float* __restrict__ out)
{
    extern __shared__ unsigned char sm[];
    const uint32_t smb = smem_to_u32(sm);
    const int tid  = threadIdx.x;
    const int wid  = tid >> 5;
    const int lane = tid & 31;
    const int qt   = lane & 3;
    const int grp  = lane >> 2;

    // ---- stage 13 weight matrices as bf16 hi/lo, [n][k] row-major, SW128 ----
    for (int idx = tid; idx < 13 * 4096; idx += TPB) {
        int mat = idx >> 12, e = idx & 4095;
        float v = (mat < 7) ? Wn_g[mat * 4096 + e] : Ws_g[(mat - 7) * 4096 + e];
        __nv_bfloat16 hb = __float2bfloat16(v);
        __nv_bfloat16 lb = __float2bfloat16(v - __bfloat162float(hb));
        int n = e >> 6, k = e & 63;
        uint32_t sw = SMEM_SWIZZLE_128B((uint32_t)(n * 128 + k * 2));
        uint32_t base = OFF_W + (uint32_t)mat * 16384;
        *reinterpret_cast<__nv_bfloat16*>(sm + base + sw)        = hb;
        *reinterpret_cast<__nv_bfloat16*>(sm + base + 8192 + sw) = lb;
    }
    for (int i = tid; i < 448; i += TPB)
        reinterpret_cast<float*>(sm + OFF_BN)[i] = bn_g[i];
    for (int i = tid; i < 384; i += TPB)
        reinterpret_cast<float*>(sm + OFF_BS)[i] = bs_g[i];
    __syncthreads();

    // per-thread ldmatrix.x4 swizzled offsets (k halves 0-31 / 32-63)
    const int r8 = lane & 7, b4 = lane >> 3;
    const uint32_t soff0 = (uint32_t)(r8 * 128 + ((b4 * 16)      ^ (r8 * 16)));
    const uint32_t soff1 = (uint32_t)(r8 * 128 + ((b4 * 16 + 64) ^ (r8 * 16)));

    const float* bn = reinterpret_cast<const float*>(sm + OFF_BN);
    const float* bs = reinterpret_cast<const float*>(sm + OFF_BS);
    const uint32_t w0 = smb + OFF_W;

    // warps are independent: global warp-strided loop over 16-row groups
    const int gw = blockIdx.x * (TPB / 32) + wid;

    for (int g = gw; g < NGROUPS; g += WSTEP) {
        const size_t gr0 = (size_t)g * 16 + grp;
        const size_t gr1 = gr0 + 8;

        Frag A0, A1;   // two slots; h_t overwrites the slot holding h_{t-2}

        // ---- load x -> A0 (hi/lo) directly from gmem ----
        {
            const float* xr0 = x + gr0 * 64;
            const float* xr1 = x + gr1 * 64;
#pragma unroll
            for (int kt = 0; kt < 4; ++kt) {
                const int c = 16 * kt + 2 * qt;
                float2 p0 = *reinterpret_cast<const float2*>(xr0 + c);
                float2 p1 = *reinterpret_cast<const float2*>(xr1 + c);
                float2 p2 = *reinterpret_cast<const float2*>(xr0 + c + 8);
                float2 p3 = *reinterpret_cast<const float2*>(xr1 + c + 8);
                pack_split(p0.x, p0.y, A0.h[kt][0], A0.l[kt][0]);
                pack_split(p1.x, p1.y, A0.h[kt][1], A0.l[kt][1]);
                pack_split(p2.x, p2.y, A0.h[kt][2], A0.l[kt][2]);
                pack_split(p3.x, p3.y, A0.h[kt][3], A0.l[kt][3]);
            }
        }

        float* o0 = out + gr0 * 64;
        float* o1 = out + gr1 * 64;

        // layer t: Ap = h_{t-1}, Aio = h_{t-2} -> h_t
        layer_step<false, false>(A0, A1, w0 + 0 * 16384, 0,
                                 bn + 0 * 64, bs, soff0, soff1, qt, o0, o1);           // h1 -> A1
        layer_step<true,  false>(A1, A0, w0 + 1 * 16384, w0 + 7 * 16384,
                                 bn + 1 * 64, bs + 0 * 64, soff0, soff1, qt, o0, o1);  // h2 -> A0
        layer_step<true,  false>(A0, A1, w0 + 2 * 16384, w0 + 8 * 16384,
                                 bn + 2 * 64, bs + 1 * 64, soff0, soff1, qt, o0, o1);  // h3 -> A1
        layer_step<true,  false>(A1, A0, w0 + 3 * 16384, w0 + 9 * 16384,
                                 bn + 3 * 64, bs + 2 * 64, soff0, soff1, qt, o0, o1);  // h4 -> A0
        layer_step<true,  false>(A0, A1, w0 + 4 * 16384, w0 + 10 * 16384,
                                 bn + 4 * 64, bs + 3 * 64, soff0, soff1, qt, o0, o1);  // h5 -> A1
        layer_step<true,  false>(A1, A0, w0 + 5 * 16384, w0 + 11 * 16384,
                                 bn + 5 * 64, bs + 4 * 64, soff0, soff1, qt, o0, o1);  // h6 -> A0
        layer_step<true,  true >(A0, A1, w0 + 6 * 16384, w0 + 12 * 16384,
                                 bn + 6 * 64, bs + 5 * 64, soff0, soff1, qt, o0, o1);  // h7 -> out
    }
}

extern "C" void kernel_launch(void* const* d_in, const int* in_sizes, int n_in,
                              void* d_out, int out_size)
{
    const float* x  = (const float*)d_in[0];
    const float* Wn = (const float*)d_in[1];
    const float* bn = (const float*)d_in[2];
    const float* Ws = (const float*)d_in[3];
    const float* bs = (const float*)d_in[4];
    float* out = (float*)d_out;

    cudaFuncSetAttribute(nn_mma_kernel,
                         cudaFuncAttributeMaxDynamicSharedMemorySize, SMEM_TOTAL);
    nn_mma_kernel<<<GRID, TPB, SMEM_TOTAL>>>(x, Wn, bn, Ws, bs, out);
}